// round 1
// baseline (speedup 1.0000x reference)
#include <cuda_runtime.h>

// 2-layer LSTM scan: B=1024, H=64, S=512, input dim 1, future_preds=0.
// 128 persistent CTAs x 256 threads; CTA owns 8 batch elements for all 512 steps.
// Thread r owns gate-row r: W_hh1[r][:] (64), W_ih2[r][:] (64), W_hh2[r][:] (64)
// kept in registers for the whole kernel. States h1/c1/h2/c2 + gates in SMEM.

#define HID 64
#define G4  256   // 4*H
#define BB  8     // batch elements per block
#define TPB 256
#define BATCH 1024
#define SEQ 512

__device__ __forceinline__ float fsigmoid(float x) {
    return __fdividef(1.0f, 1.0f + __expf(-x));
}
__device__ __forceinline__ float ftanh(float x) {
    float xx = fminf(fmaxf(x, -15.0f), 15.0f);
    float e = __expf(2.0f * xx);
    return __fdividef(e - 1.0f, e + 1.0f);
}

__global__ __launch_bounds__(TPB, 1)
void lstm_kernel(const float* __restrict__ input,
                 const float* __restrict__ W_ih1, const float* __restrict__ W_hh1,
                 const float* __restrict__ b_ih1, const float* __restrict__ b_hh1,
                 const float* __restrict__ W_ih2, const float* __restrict__ W_hh2,
                 const float* __restrict__ b_ih2, const float* __restrict__ b_hh2,
                 const float* __restrict__ W_lin, const float* __restrict__ b_lin,
                 float* __restrict__ out)
{
    __shared__ float xs[BB][SEQ];                       // staged inputs (16 KB)
    __shared__ float g1[BB][G4];                        // layer-1 gates (8 KB)
    __shared__ float g2[BB][G4];                        // layer-2 gates (8 KB)
    __shared__ __align__(16) float h1s[BB][HID];
    __shared__ __align__(16) float c1s[BB][HID];
    __shared__ __align__(16) float h2s[BB][HID];
    __shared__ __align__(16) float c2s[BB][HID];
    __shared__ float wl[HID];
    __shared__ float blin;

    const int r  = threadIdx.x;        // gate row 0..255 this thread owns
    const int b0 = blockIdx.x * BB;    // first batch element of this block

    // ---- Load this row's weights into registers (loop-invariant, one time) ----
    float wA[HID], wB[HID], wC[HID];
    #pragma unroll
    for (int k = 0; k < HID; k++) {
        wA[k] = W_hh1[r * HID + k];
        wB[k] = W_ih2[r * HID + k];
        wC[k] = W_hh2[r * HID + k];
    }
    const float bias1 = b_ih1[r] + b_hh1[r];
    const float bias2 = b_ih2[r] + b_hh2[r];
    const float wx    = W_ih1[r];      // input dim is 1

    // ---- Stage inputs + init state ----
    for (int idx = r; idx < BB * SEQ; idx += TPB)
        xs[idx / SEQ][idx % SEQ] = input[b0 * SEQ + idx];   // coalesced
    for (int idx = r; idx < BB * HID; idx += TPB) {
        int b = idx / HID, j = idx % HID;
        h1s[b][j] = 0.f; c1s[b][j] = 0.f; h2s[b][j] = 0.f; c2s[b][j] = 0.f;
    }
    if (r < HID) wl[r] = W_lin[r];
    if (r == 0)  blin  = b_lin[0];
    __syncthreads();

    const int wid = r >> 5, lane = r & 31;

    for (int t = 0; t < SEQ; t++) {
        // ---- Phase A: layer-1 gates: g1[b][r] = bias1 + wx*x + wA . h1[b] ----
        #pragma unroll 1
        for (int b = 0; b < BB; b++) {
            float acc = fmaf(wx, xs[b][t], bias1);
            const float4* hp = (const float4*)h1s[b];
            #pragma unroll
            for (int k4 = 0; k4 < HID / 4; k4++) {
                float4 hv = hp[k4];
                acc = fmaf(wA[4*k4+0], hv.x, acc);
                acc = fmaf(wA[4*k4+1], hv.y, acc);
                acc = fmaf(wA[4*k4+2], hv.z, acc);
                acc = fmaf(wA[4*k4+3], hv.w, acc);
            }
            g1[b][r] = acc;
        }
        __syncthreads();

        // ---- Act1: update h1, c1 (512 tasks over 256 threads) ----
        #pragma unroll
        for (int rep = 0; rep < 2; rep++) {
            int task = r + rep * TPB;
            int b = task >> 6, j = task & 63;
            float gi = g1[b][j],           gf = g1[b][HID   + j];
            float gg = g1[b][2*HID + j],   go = g1[b][3*HID + j];
            float cn = fsigmoid(gf) * c1s[b][j] + fsigmoid(gi) * ftanh(gg);
            c1s[b][j] = cn;
            h1s[b][j] = fsigmoid(go) * ftanh(cn);
        }
        __syncthreads();

        // ---- Phase B: layer-2 gates: g2[b][r] = bias2 + wB . h1[b] + wC . h2[b] ----
        #pragma unroll 1
        for (int b = 0; b < BB; b++) {
            float acc = bias2;
            const float4* hp1 = (const float4*)h1s[b];
            const float4* hp2 = (const float4*)h2s[b];
            #pragma unroll
            for (int k4 = 0; k4 < HID / 4; k4++) {
                float4 v1 = hp1[k4];
                float4 v2 = hp2[k4];
                acc = fmaf(wB[4*k4+0], v1.x, acc);
                acc = fmaf(wB[4*k4+1], v1.y, acc);
                acc = fmaf(wB[4*k4+2], v1.z, acc);
                acc = fmaf(wB[4*k4+3], v1.w, acc);
                acc = fmaf(wC[4*k4+0], v2.x, acc);
                acc = fmaf(wC[4*k4+1], v2.y, acc);
                acc = fmaf(wC[4*k4+2], v2.z, acc);
                acc = fmaf(wC[4*k4+3], v2.w, acc);
            }
            g2[b][r] = acc;
        }
        __syncthreads();

        // ---- Act2: update h2, c2 ----
        #pragma unroll
        for (int rep = 0; rep < 2; rep++) {
            int task = r + rep * TPB;
            int b = task >> 6, j = task & 63;
            float gi = g2[b][j],           gf = g2[b][HID   + j];
            float gg = g2[b][2*HID + j],   go = g2[b][3*HID + j];
            float cn = fsigmoid(gf) * c2s[b][j] + fsigmoid(gi) * ftanh(gg);
            c2s[b][j] = cn;
            h2s[b][j] = fsigmoid(go) * ftanh(cn);
        }
        __syncthreads();

        // ---- Output: warp w reduces batch element b=w: out = wl . h2[b] + blin ----
        {
            int b = wid;
            float v = wl[lane] * h2s[b][lane] + wl[lane + 32] * h2s[b][lane + 32];
            #pragma unroll
            for (int off = 16; off; off >>= 1)
                v += __shfl_down_sync(0xFFFFFFFFu, v, off);
            if (lane == 0) out[(b0 + b) * SEQ + t] = v + blin;
        }
        // No barrier needed before next Phase A:
        //  - next writes touch g1 (last read before sync2 this step)
        //  - h2 (read here) is next written only after 3 more barriers (next Act2)
    }
}

extern "C" void kernel_launch(void* const* d_in, const int* in_sizes, int n_in,
                              void* d_out, int out_size) {
    (void)in_sizes; (void)n_in; (void)out_size;
    const float* input = (const float*)d_in[0];
    const float* W_ih1 = (const float*)d_in[1];
    const float* W_hh1 = (const float*)d_in[2];
    const float* b_ih1 = (const float*)d_in[3];
    const float* b_hh1 = (const float*)d_in[4];
    const float* W_ih2 = (const float*)d_in[5];
    const float* W_hh2 = (const float*)d_in[6];
    const float* b_ih2 = (const float*)d_in[7];
    const float* b_hh2 = (const float*)d_in[8];
    const float* W_lin = (const float*)d_in[9];
    const float* b_lin = (const float*)d_in[10];
    float* out = (float*)d_out;

    lstm_kernel<<<BATCH / BB, TPB>>>(input, W_ih1, W_hh1, b_ih1, b_hh1,
                                     W_ih2, W_hh2, b_ih2, b_hh2,
                                     W_lin, b_lin, out);
}